// round 14
// baseline (speedup 1.0000x reference)
#include <cuda_runtime.h>
#include <cuda_fp16.h>
#include <cstdint>

// GoalDecoderLSTM, B=131072, H=64, E=16, SEQ=30 — fp16 HMMA.
// R14 = R13 (B in registers, ldmatrix A, fp32 tanh.approx epilogue, parallel
// tail, m-stagger, occ 2, lean tail) + zero-register overlap:
//   * cross-barrier split prefetch: LDSM kc0..3 of next step's mm=0 between
//     barrier A and the tail (N h-part complete at barrier A; tail writes only
//     x words 32..39), kc4 after barrier B. A regs are dead during the tail.
//   * tail x' pair stored as one STS.64.
// CTA = 64 elems, 8 warps, occ 2. Warp w owns j in [8w,8w+8) (all 4 gates).

#define TB    64
#define SEQ   30
#define NTHR  256
#define HROW  44

// SMEM layout
#define SM_H       0                        // 2 bufs * 64*44*4 = 2*11264
#define HBUF_BYTES (TB * HROW * 4)
#define SM_F       (2*HBUF_BYTES)           // 22528
// float indices within sF
#define FI_BC    0      // 256
#define FI_W2P   256    // 128
#define FI_MG    384    // 128
#define FI_M2    512    // 4
#define FI_CV    516    // 2
#define FI_CG    518    // 2
#define FI_WSE4  520    // 32
#define FI_BSE2  552    // 16
#define FI_RELP  568    // 8 warps * 65 float2 = 1040 floats
#define RELPW    130    // floats per warp slot (padded: breaks 128-word alias)
#define FI_GOC   (FI_RELP + 8*RELPW)   // 128 floats
#define SF_FLOATS (FI_GOC + 128)
#define SMEM_BYTES (SM_F + SF_FLOATS*4)

typedef uint32_t u32;
typedef unsigned long long u64;

// ---- device staging (prep -> main) ----
__device__ __align__(16) u64 g_Bfrag[160 * 32];   // frag f = wid*20 + kc*4 + t
__device__ float g_bc[256];
__device__ float g_w2p[128];
__device__ float g_Mg[128];
__device__ float g_M2[4];
__device__ float g_cv[2];
__device__ float g_cg[2];
__device__ float g_wse4[32];
__device__ float g_bse2[16];

// ---- helpers ----
__device__ __forceinline__ u32 f16pack(float a, float b) {
    __half2 h = __floats2half2_rn(a, b);    // a -> low, b -> high
    return *(u32*)&h;
}
__device__ __forceinline__ void mma16816(float* d, const u32* a, u32 b0, u32 b1) {
    asm volatile("mma.sync.aligned.m16n8k16.row.col.f32.f16.f16.f32 "
        "{%0,%1,%2,%3}, {%4,%5,%6,%7}, {%8,%9}, {%0,%1,%2,%3};"
        : "+f"(d[0]), "+f"(d[1]), "+f"(d[2]), "+f"(d[3])
        : "r"(a[0]), "r"(a[1]), "r"(a[2]), "r"(a[3]), "r"(b0), "r"(b1));
}
__device__ __forceinline__ void ldsm_x4(u32* a, u32 addr) {
    asm volatile("ldmatrix.sync.aligned.m8n8.x4.shared.b16 {%0,%1,%2,%3}, [%4];"
        : "=r"(a[0]), "=r"(a[1]), "=r"(a[2]), "=r"(a[3]) : "r"(addr));
}
__device__ __forceinline__ float tanh_hw(float x) {
    float r; asm("tanh.approx.f32 %0, %1;" : "=f"(r) : "f"(x)); return r;
}
__device__ __forceinline__ float lstm_unit(float iv, float fv, float gv, float ov, float& cst) {
    float si = fmaf(0.5f, tanh_hw(0.5f * iv), 0.5f);
    float sf = fmaf(0.5f, tanh_hw(0.5f * fv), 0.5f);
    float tg = tanh_hw(gv);
    float so = fmaf(0.5f, tanh_hw(0.5f * ov), 0.5f);
    float cn = fmaf(sf, cst, si * tg);
    cst = cn;
    return so * tanh_hw(cn);
}

// ============================================================================
// Prep: fold small matrices; build B fragments (fp16, per-warp-slice order)
// ============================================================================
__global__ void prep_kernel(const float* __restrict__ W_ih, const float* __restrict__ W_hh,
                            const float* __restrict__ b_ih, const float* __restrict__ b_hh,
                            const float* __restrict__ W_h2p, const float* __restrict__ b_h2p,
                            const float* __restrict__ W_goal, const float* __restrict__ b_goal,
                            const float* __restrict__ W_abs, const float* __restrict__ b_abs,
                            const float* __restrict__ W_se, const float* __restrict__ b_se)
{
    int tid = threadIdx.x;
    // frag f = w*20 + kc*4 + t  (w = warp slice 0..7, j in [8w, 8w+8))
    for (int idx = tid; idx < 160 * 32; idx += NTHR) {
        int f = idx >> 5, l = idx & 31;
        int w = f / 20, r = f % 20, kc = r >> 2, t = r & 3;
        int jj = l >> 2, c4 = l & 3;
        int j = 8 * w + jj;
        int row = t * 64 + j;
        int k0 = 16 * kc + 2 * c4;
        float v[4];
        #pragma unroll
        for (int i = 0; i < 4; i++) {
            int k = k0 + (i & 1) + (i >> 1) * 8;
            v[i] = (k < 64) ? W_hh[row * 64 + k] : W_ih[row * 16 + (k - 64)];
        }
        __half2 p0 = __floats2half2_rn(v[0], v[1]);
        __half2 p1 = __floats2half2_rn(v[2], v[3]);
        g_Bfrag[idx] = (u64)*(u32*)&p0 | ((u64)*(u32*)&p1 << 32);
    }
    {
        int j = tid & 63, t = tid >> 6, row = t * 64 + j;
        g_bc[tid] = b_ih[row] + b_hh[row];
    }
    if (tid < 64) {
        g_w2p[2 * tid]     = W_h2p[tid];
        g_w2p[2 * tid + 1] = W_h2p[192 + tid];
    }
    if (tid < 128) {
        int r = tid >> 6, j = tid & 63;
        float s = 0.f;
        for (int m = 0; m < 64; m++) s += W_h2p[r * 192 + 128 + m] * W_goal[m * 64 + j];
        g_Mg[tid] = s;
    }
    if (tid < 4) {
        int r = tid >> 1, c = tid & 1;
        float s = 0.f;
        for (int m = 0; m < 64; m++) s += W_h2p[r * 192 + 64 + m] * W_abs[m * 2 + c];
        g_M2[tid] = s;
    }
    if (tid < 2) {
        float s = b_h2p[tid];
        for (int m = 0; m < 64; m++) s += W_h2p[tid * 192 + 64 + m] * b_abs[m];
        g_cv[tid] = s;
        float s2 = 0.f;
        for (int m = 0; m < 64; m++) s2 += W_h2p[tid * 192 + 128 + m] * b_goal[m];
        g_cg[tid] = s2;
    }
    if (tid < 8) {
        g_wse4[tid * 4 + 0] = W_se[(2 * tid) * 2 + 0];
        g_wse4[tid * 4 + 1] = W_se[(2 * tid) * 2 + 1];
        g_wse4[tid * 4 + 2] = W_se[(2 * tid + 1) * 2 + 0];
        g_wse4[tid * 4 + 3] = W_se[(2 * tid + 1) * 2 + 1];
        g_bse2[tid * 2 + 0] = b_se[2 * tid];
        g_bse2[tid * 2 + 1] = b_se[2 * tid + 1];
    }
}

// ============================================================================
// Main kernel: 64 elems/CTA, 8 warps, 2 CTAs/SM, B in registers
// ============================================================================
__global__ void __launch_bounds__(NTHR, 2)
lstm_main(const float* __restrict__ traj_abs, const float* __restrict__ traj_rel,
          const float* __restrict__ h0g, const float* __restrict__ c0g,
          const float* __restrict__ goals, float* __restrict__ out, int Btot)
{
    extern __shared__ __align__(16) char smem[];
    float* sF = (float*)(smem + SM_F);
    const int tid = threadIdx.x, l = tid & 31, wid = tid >> 5;
    const int c4 = l & 3, q = l >> 2;
    const int b0 = blockIdx.x * TB;

    // ---- fill sF from staging ----
    for (int i = tid; i < 256; i += NTHR) sF[FI_BC + i] = g_bc[i];
    if (tid < 128) { sF[FI_W2P + tid] = g_w2p[tid]; sF[FI_MG + tid] = g_Mg[tid]; }
    if (tid < 4)  sF[FI_M2 + tid] = g_M2[tid];
    if (tid < 2)  { sF[FI_CV + tid] = g_cv[tid]; sF[FI_CG + tid] = g_cg[tid]; }
    if (tid < 32) sF[FI_WSE4 + tid] = g_wse4[tid];
    if (tid < 16) sF[FI_BSE2 + tid] = g_bse2[tid];
    __syncthreads();

    // ---- B fragments into registers (persistent) ----
    u64 Breg[5][4];
    {
        const u64* gB = g_Bfrag + (size_t)wid * 20 * 32 + l;
        #pragma unroll
        for (int kc = 0; kc < 5; kc++)
            #pragma unroll
            for (int t = 0; t < 4; t++)
                Breg[kc][t] = gB[(kc * 4 + t) * 32];
    }
    // per-warp-lane constants: biases + w2 pairs for j0 = 8*wid + 2*c4
    const int j0 = 8 * wid + 2 * c4;
    const float2 bI = *(const float2*)(sF + FI_BC + j0);
    const float2 bF = *(const float2*)(sF + FI_BC + 64 + j0);
    const float2 bG = *(const float2*)(sF + FI_BC + 128 + j0);
    const float2 bO = *(const float2*)(sF + FI_BC + 192 + j0);
    const float4 w2q = *(const float4*)(sF + FI_W2P + 2 * j0);
    const int wp = 4 * wid + c4;            // h' store word position (plain)

    // u32 shared base of H buffers
    const u32 Hbase = (u32)__cvta_generic_to_shared(smem);

    // per-mm offsets (m = (mm+wid)&3 stagger)
    int aofs[4], hoff[4], roff[4];
    {
        const int lrow_loc = ((l >> 3) & 1) * 8 + (l & 7);
        const int khalf = l >> 4;
        #pragma unroll
        for (int mm = 0; mm < 4; mm++) {
            int m = (mm + wid) & 3;
            aofs[mm] = (16 * m + lrow_loc) * (HROW * 4) + khalf * 16;
            hoff[mm] = (16 * m + q) * HROW + wp;
            roff[mm] = 16 * m + q;
        }
    }

    // ---- init H buffer 0 (plain fp16x2 word layout) ----
    {
        u32* H0 = (u32*)(smem + SM_H);
        for (int idx = tid; idx < TB * 32; idx += NTHR) {
            int row = idx >> 5, w = idx & 31;
            float2 hv = *(const float2*)(h0g + (size_t)(b0 + row) * 64 + 2 * w);
            H0[row * HROW + w] = f16pack(hv.x, hv.y);
        }
        for (int idx = tid; idx < TB * 8; idx += NTHR) {
            int row = idx >> 3, p = idx & 7;
            float2 tr = *(const float2*)(traj_rel + (size_t)(b0 + row) * 2);
            float4 w4 = *(const float4*)(sF + FI_WSE4 + 4 * p);
            float xa = w4.x * tr.x + w4.y * tr.y + sF[FI_BSE2 + 2 * p];
            float xb = w4.z * tr.x + w4.w * tr.y + sF[FI_BSE2 + 2 * p + 1];
            xa = (xa > 0.f) ? xa : 0.01f * xa;
            xb = (xb > 0.f) ? xb : 0.01f * xb;
            H0[row * HROW + 32 + p] = f16pack(xa, xb);
        }
    }

    // ---- c-state: creg[mm][rh][jj] ----
    float creg[4][2][2];
    #pragma unroll
    for (int mm = 0; mm < 4; mm++)
        #pragma unroll
        for (int rh = 0; rh < 2; rh++) {
            int row = roff[mm] + 8 * rh;
            float2 cv2 = *(const float2*)(c0g + (size_t)(b0 + row) * 64 + j0);
            creg[mm][rh][0] = cv2.x; creg[mm][rh][1] = cv2.y;
        }

    // ---- row-owner derived state (goal fold) -> SMEM (tid < 64, row = tid) ----
    if (tid < TB) {
        const int row = tid;
        float s0 = sF[FI_CG], s1 = sF[FI_CG + 1];
        const float* gp = goals + (size_t)(b0 + row) * 64;
        #pragma unroll 8
        for (int k = 0; k < 64; k++) {
            float gv = gp[k];
            s0 += sF[FI_MG + k] * gv;
            s1 += sF[FI_MG + 64 + k] * gv;
        }
        sF[FI_GOC + 2 * row] = s0; sF[FI_GOC + 2 * row + 1] = s1;
    }
    __syncthreads();

    // ---- tail state in registers ----
    const int trow = tid >> 2;           // tail: row owned by this thread
    const int tpart = tid & 3;           // tail: which partial pair
    const float cv0 = sF[FI_CV], cv1 = sF[FI_CV + 1];
    const float m200 = sF[FI_M2], m201 = sF[FI_M2 + 1];
    const float m210 = sF[FI_M2 + 2], m211 = sF[FI_M2 + 3];
    const float goc0 = sF[FI_GOC + 2 * trow], goc1 = sF[FI_GOC + 2 * trow + 1];
    const float4 wse_a = *(const float4*)(sF + FI_WSE4 + 4 * (2 * tpart));
    const float4 wse_b = *(const float4*)(sF + FI_WSE4 + 4 * (2 * tpart + 1));
    const float2 bse_a = *(const float2*)(sF + FI_BSE2 + 2 * (2 * tpart));
    const float2 bse_b = *(const float2*)(sF + FI_BSE2 + 2 * (2 * tpart + 1));
    // abs-position: private per tail thread (all 4 parts update identically)
    float ab0 = traj_abs[(size_t)(b0 + trow) * 2];
    float ab1 = traj_abs[(size_t)(b0 + trow) * 2 + 1];

    // ---- prologue: A fragments for (s=0, mm=0) ----
    u32 A[5][4];
    {
        const u32 ab = Hbase + aofs[0];
        #pragma unroll
        for (int kc = 0; kc < 5; kc++)
            ldsm_x4(A[kc], ab + kc * 32);
    }

    #pragma unroll 1
    for (int s = 0; s < SEQ; s++) {
        const u32 Hu = Hbase + (s & 1) * HBUF_BYTES;
        const u32 Nu = Hbase + ((s + 1) & 1) * HBUF_BYTES;
        u32* N = (u32*)(smem + SM_H) + ((s + 1) & 1) * (HBUF_BYTES / 4);

        #pragma unroll
        for (int mm = 0; mm < 4; mm++) {
            // ---- A fragments (mm=0 already prefetched across the barrier) ----
            if (mm > 0) {
                const u32 ab = Hu + aofs[mm];
                #pragma unroll
                for (int kc = 0; kc < 5; kc++)
                    ldsm_x4(A[kc], ab + kc * 32);
            }
            // ---- MMA: bias-initialized accumulators ----
            float acc[4][4] = {
                { bI.x, bI.y, bI.x, bI.y },
                { bF.x, bF.y, bF.x, bF.y },
                { bG.x, bG.y, bG.x, bG.y },
                { bO.x, bO.y, bO.x, bO.y },
            };
            #pragma unroll
            for (int kc = 0; kc < 5; kc++)
                #pragma unroll
                for (int t = 0; t < 4; t++)
                    mma16816(acc[t], A[kc], (u32)Breg[kc][t], (u32)(Breg[kc][t] >> 32));

            // ---- epilogue ----
            float rpm[2][2];
            #pragma unroll
            for (int rh = 0; rh < 2; rh++) {
                float h0v = lstm_unit(acc[0][2 * rh], acc[1][2 * rh],
                                      acc[2][2 * rh], acc[3][2 * rh], creg[mm][rh][0]);
                float h1v = lstm_unit(acc[0][2 * rh + 1], acc[1][2 * rh + 1],
                                      acc[2][2 * rh + 1], acc[3][2 * rh + 1], creg[mm][rh][1]);
                rpm[rh][0] = w2q.x * h0v + w2q.z * h1v;
                rpm[rh][1] = w2q.y * h0v + w2q.w * h1v;
                N[hoff[mm] + 8 * HROW * rh] = f16pack(h0v, h1v);
            }
            // quad butterfly -> warp partial for this warp's 8 j's
            #pragma unroll
            for (int rh = 0; rh < 2; rh++) {
                #pragma unroll
                for (int ax = 0; ax < 2; ax++) {
                    float v = rpm[rh][ax];
                    v += __shfl_xor_sync(0xFFFFFFFFu, v, 1);
                    v += __shfl_xor_sync(0xFFFFFFFFu, v, 2);
                    rpm[rh][ax] = v;
                }
            }
            if (c4 == 0) {
                #pragma unroll
                for (int rh = 0; rh < 2; rh++) {
                    int row = roff[mm] + 8 * rh;
                    *(float2*)(sF + FI_RELP + wid * RELPW + 2 * row) =
                        make_float2(rpm[rh][0], rpm[rh][1]);
                }
            }
        }
        __syncthreads();   // barrier A: h' + RELP visible

        // ---- cross-barrier prefetch: next step's mm=0, h-part (kc0..3).
        //      N h-part is complete at barrier A; the tail writes only the x
        //      words (32..39 of each row) -> disjoint. A regs dead until then.
        if (s < SEQ - 1) {
            const u32 ab = Nu + aofs[0];
            #pragma unroll
            for (int kc = 0; kc < 4; kc++)
                ldsm_x4(A[kc], ab + kc * 32);
        }

        // ---- rel finalization: 4 threads per row (row=tid>>2, part=tid&3) ----
        {
            float2 pa = *(const float2*)(sF + FI_RELP + (2 * tpart) * RELPW + 2 * trow);
            float2 pb = *(const float2*)(sF + FI_RELP + (2 * tpart + 1) * RELPW + 2 * trow);
            float r0 = pa.x + pb.x, r1 = pa.y + pb.y;
            r0 += __shfl_xor_sync(0xFFFFFFFFu, r0, 1);
            r0 += __shfl_xor_sync(0xFFFFFFFFu, r0, 2);
            r1 += __shfl_xor_sync(0xFFFFFFFFu, r1, 1);
            r1 += __shfl_xor_sync(0xFFFFFFFFu, r1, 2);
            r0 += cv0 + goc0 + m200 * ab0 + m201 * ab1;
            r1 += cv1 + goc1 + m210 * ab0 + m211 * ab1;
            if (tpart == 0)
                *(float2*)(out + ((size_t)s * Btot + b0 + trow) * 2) = make_float2(r0, r1);
            ab0 += r0; ab1 += r1;
            if (s < SEQ - 1) {
                float xa = wse_a.x * r0 + wse_a.y * r1 + bse_a.x;
                float xb = wse_a.z * r0 + wse_a.w * r1 + bse_a.y;
                xa = (xa > 0.f) ? xa : 0.01f * xa;
                xb = (xb > 0.f) ? xb : 0.01f * xb;
                float xc = wse_b.x * r0 + wse_b.y * r1 + bse_b.x;
                float xd = wse_b.z * r0 + wse_b.w * r1 + bse_b.y;
                xc = (xc > 0.f) ? xc : 0.01f * xc;
                xd = (xd > 0.f) ? xd : 0.01f * xd;
                u64 xw = (u64)f16pack(xa, xb) | ((u64)f16pack(xc, xd) << 32);
                *(u64*)(N + trow * HROW + 32 + 2 * tpart) = xw;   // one STS.64
            }
        }
        __syncthreads();   // barrier B: x' visible

        // ---- complete next step's mm=0 A: kc4 (x chunk) ----
        if (s < SEQ - 1)
            ldsm_x4(A[4], Nu + aofs[0] + 4 * 32);
    }
}

// ============================================================================
extern "C" void kernel_launch(void* const* d_in, const int* in_sizes, int n_in,
                              void* d_out, int out_size)
{
    const float* traj_abs = (const float*)d_in[0];
    const float* traj_rel = (const float*)d_in[1];
    const float* h0       = (const float*)d_in[2];
    const float* c0       = (const float*)d_in[3];
    const float* goals    = (const float*)d_in[4];
    const float* W_ih     = (const float*)d_in[5];
    const float* W_hh     = (const float*)d_in[6];
    const float* b_ih     = (const float*)d_in[7];
    const float* b_hh     = (const float*)d_in[8];
    const float* W_se     = (const float*)d_in[9];
    const float* b_se     = (const float*)d_in[10];
    const float* W_h2p    = (const float*)d_in[11];
    const float* b_h2p    = (const float*)d_in[12];
    const float* W_goal   = (const float*)d_in[13];
    const float* b_goal   = (const float*)d_in[14];
    const float* W_abs    = (const float*)d_in[15];
    const float* b_abs    = (const float*)d_in[16];

    int B = in_sizes[2] / 64;

    cudaFuncSetAttribute(lstm_main, cudaFuncAttributeMaxDynamicSharedMemorySize, SMEM_BYTES);

    prep_kernel<<<1, NTHR>>>(W_ih, W_hh, b_ih, b_hh, W_h2p, b_h2p,
                             W_goal, b_goal, W_abs, b_abs, W_se, b_se);
    lstm_main<<<B / TB, NTHR, SMEM_BYTES>>>(traj_abs, traj_rel, h0, c0, goals,
                                            (float*)d_out, B);
}

// round 15
// speedup vs baseline: 1.0514x; 1.0514x over previous
#include <cuda_runtime.h>
#include <cuda_fp16.h>
#include <cstdint>

// GoalDecoderLSTM, B=131072, H=64, E=16, SEQ=30 — fp16 HMMA.
// R15 = R13 (B in registers, ldmatrix A, parallel lean tail, m-stagger, occ 2,
// HROW=44 plain layout) with ONLY the activation epilogue changed to f16x2:
// tanh.approx.f16x2 pairs (5 tanh per unit-pair vs 10), fp32 c-recurrence,
// h' produced directly as the packed f16x2 store word.
// CTA = 64 elems, 8 warps, occ 2. Warp w owns j in [8w,8w+8) (all 4 gates).

#define TB    64
#define SEQ   30
#define NTHR  256
#define HROW  44

// SMEM layout
#define SM_H       0                        // 2 bufs * 64*44*4 = 2*11264
#define HBUF_BYTES (TB * HROW * 4)
#define SM_F       (2*HBUF_BYTES)           // 22528
// float indices within sF
#define FI_BC    0      // 256
#define FI_W2P   256    // 128
#define FI_MG    384    // 128
#define FI_M2    512    // 4
#define FI_CV    516    // 2
#define FI_CG    518    // 2
#define FI_WSE4  520    // 32
#define FI_BSE2  552    // 16
#define FI_RELP  568    // 8 warps * 65 float2 = 1040 floats
#define RELPW    130    // floats per warp slot (padded: breaks 128-word alias)
#define FI_GOC   (FI_RELP + 8*RELPW)   // 128 floats
#define SF_FLOATS (FI_GOC + 128)
#define SMEM_BYTES (SM_F + SF_FLOATS*4)

typedef uint32_t u32;
typedef unsigned long long u64;

// ---- device staging (prep -> main) ----
__device__ __align__(16) u64 g_Bfrag[160 * 32];   // frag f = wid*20 + kc*4 + t
__device__ float g_bc[256];
__device__ float g_w2p[128];
__device__ float g_Mg[128];
__device__ float g_M2[4];
__device__ float g_cv[2];
__device__ float g_cg[2];
__device__ float g_wse4[32];
__device__ float g_bse2[16];

// ---- helpers ----
__device__ __forceinline__ u32 f16pack(float a, float b) {
    u32 r; asm("cvt.rn.f16x2.f32 %0, %1, %2;" : "=r"(r) : "f"(b), "f"(a)); return r;
}
__device__ __forceinline__ float2 h2unpack(u32 v) {
    __half2 h; *(u32*)&h = v; return __half22float2(h);
}
__device__ __forceinline__ u32 tanh_h2(u32 x) {
    u32 r; asm("tanh.approx.f16x2 %0, %1;" : "=r"(r) : "r"(x)); return r;
}
__device__ __forceinline__ u32 hmul2(u32 a, u32 b) {
    u32 r; asm("mul.f16x2 %0, %1, %2;" : "=r"(r) : "r"(a), "r"(b)); return r;
}
__device__ __forceinline__ u32 hfma2(u32 a, u32 b, u32 c) {
    u32 r; asm("fma.rn.f16x2 %0, %1, %2, %3;" : "=r"(r) : "r"(a), "r"(b), "r"(c)); return r;
}
__device__ __forceinline__ void mma16816(float* d, const u32* a, u32 b0, u32 b1) {
    asm volatile("mma.sync.aligned.m16n8k16.row.col.f32.f16.f16.f32 "
        "{%0,%1,%2,%3}, {%4,%5,%6,%7}, {%8,%9}, {%0,%1,%2,%3};"
        : "+f"(d[0]), "+f"(d[1]), "+f"(d[2]), "+f"(d[3])
        : "r"(a[0]), "r"(a[1]), "r"(a[2]), "r"(a[3]), "r"(b0), "r"(b1));
}
__device__ __forceinline__ void ldsm_x4(u32* a, u32 addr) {
    asm volatile("ldmatrix.sync.aligned.m8n8.x4.shared.b16 {%0,%1,%2,%3}, [%4];"
        : "=r"(a[0]), "=r"(a[1]), "=r"(a[2]), "=r"(a[3]) : "r"(addr));
}

// ============================================================================
// Prep: fold small matrices; build B fragments (fp16, per-warp-slice order)
// ============================================================================
__global__ void prep_kernel(const float* __restrict__ W_ih, const float* __restrict__ W_hh,
                            const float* __restrict__ b_ih, const float* __restrict__ b_hh,
                            const float* __restrict__ W_h2p, const float* __restrict__ b_h2p,
                            const float* __restrict__ W_goal, const float* __restrict__ b_goal,
                            const float* __restrict__ W_abs, const float* __restrict__ b_abs,
                            const float* __restrict__ W_se, const float* __restrict__ b_se)
{
    int tid = threadIdx.x;
    // frag f = w*20 + kc*4 + t  (w = warp slice 0..7, j in [8w, 8w+8))
    for (int idx = tid; idx < 160 * 32; idx += NTHR) {
        int f = idx >> 5, l = idx & 31;
        int w = f / 20, r = f % 20, kc = r >> 2, t = r & 3;
        int jj = l >> 2, c4 = l & 3;
        int j = 8 * w + jj;
        int row = t * 64 + j;
        int k0 = 16 * kc + 2 * c4;
        float v[4];
        #pragma unroll
        for (int i = 0; i < 4; i++) {
            int k = k0 + (i & 1) + (i >> 1) * 8;
            v[i] = (k < 64) ? W_hh[row * 64 + k] : W_ih[row * 16 + (k - 64)];
        }
        __half2 p0 = __floats2half2_rn(v[0], v[1]);
        __half2 p1 = __floats2half2_rn(v[2], v[3]);
        g_Bfrag[idx] = (u64)*(u32*)&p0 | ((u64)*(u32*)&p1 << 32);
    }
    {
        int j = tid & 63, t = tid >> 6, row = t * 64 + j;
        g_bc[tid] = b_ih[row] + b_hh[row];
    }
    if (tid < 64) {
        g_w2p[2 * tid]     = W_h2p[tid];
        g_w2p[2 * tid + 1] = W_h2p[192 + tid];
    }
    if (tid < 128) {
        int r = tid >> 6, j = tid & 63;
        float s = 0.f;
        for (int m = 0; m < 64; m++) s += W_h2p[r * 192 + 128 + m] * W_goal[m * 64 + j];
        g_Mg[tid] = s;
    }
    if (tid < 4) {
        int r = tid >> 1, c = tid & 1;
        float s = 0.f;
        for (int m = 0; m < 64; m++) s += W_h2p[r * 192 + 64 + m] * W_abs[m * 2 + c];
        g_M2[tid] = s;
    }
    if (tid < 2) {
        float s = b_h2p[tid];
        for (int m = 0; m < 64; m++) s += W_h2p[tid * 192 + 64 + m] * b_abs[m];
        g_cv[tid] = s;
        float s2 = 0.f;
        for (int m = 0; m < 64; m++) s2 += W_h2p[tid * 192 + 128 + m] * b_goal[m];
        g_cg[tid] = s2;
    }
    if (tid < 8) {
        g_wse4[tid * 4 + 0] = W_se[(2 * tid) * 2 + 0];
        g_wse4[tid * 4 + 1] = W_se[(2 * tid) * 2 + 1];
        g_wse4[tid * 4 + 2] = W_se[(2 * tid + 1) * 2 + 0];
        g_wse4[tid * 4 + 3] = W_se[(2 * tid + 1) * 2 + 1];
        g_bse2[tid * 2 + 0] = b_se[2 * tid];
        g_bse2[tid * 2 + 1] = b_se[2 * tid + 1];
    }
}

// ============================================================================
// Main kernel: 64 elems/CTA, 8 warps, 2 CTAs/SM, B in registers
// ============================================================================
__global__ void __launch_bounds__(NTHR, 2)
lstm_main(const float* __restrict__ traj_abs, const float* __restrict__ traj_rel,
          const float* __restrict__ h0g, const float* __restrict__ c0g,
          const float* __restrict__ goals, float* __restrict__ out, int Btot)
{
    extern __shared__ __align__(16) char smem[];
    float* sF = (float*)(smem + SM_F);
    const int tid = threadIdx.x, l = tid & 31, wid = tid >> 5;
    const int c4 = l & 3, q = l >> 2;
    const int b0 = blockIdx.x * TB;

    // ---- fill sF from staging ----
    for (int i = tid; i < 256; i += NTHR) sF[FI_BC + i] = g_bc[i];
    if (tid < 128) { sF[FI_W2P + tid] = g_w2p[tid]; sF[FI_MG + tid] = g_Mg[tid]; }
    if (tid < 4)  sF[FI_M2 + tid] = g_M2[tid];
    if (tid < 2)  { sF[FI_CV + tid] = g_cv[tid]; sF[FI_CG + tid] = g_cg[tid]; }
    if (tid < 32) sF[FI_WSE4 + tid] = g_wse4[tid];
    if (tid < 16) sF[FI_BSE2 + tid] = g_bse2[tid];
    __syncthreads();

    // ---- B fragments into registers (persistent) ----
    u64 Breg[5][4];
    {
        const u64* gB = g_Bfrag + (size_t)wid * 20 * 32 + l;
        #pragma unroll
        for (int kc = 0; kc < 5; kc++)
            #pragma unroll
            for (int t = 0; t < 4; t++)
                Breg[kc][t] = gB[(kc * 4 + t) * 32];
    }
    // per-warp-lane constants: biases + w2 pairs for j0 = 8*wid + 2*c4
    const int j0 = 8 * wid + 2 * c4;
    const float2 bI = *(const float2*)(sF + FI_BC + j0);
    const float2 bF = *(const float2*)(sF + FI_BC + 64 + j0);
    const float2 bG = *(const float2*)(sF + FI_BC + 128 + j0);
    const float2 bO = *(const float2*)(sF + FI_BC + 192 + j0);
    const float4 w2q = *(const float4*)(sF + FI_W2P + 2 * j0);
    const int wp = 4 * wid + c4;            // h' store word position (plain)

    // u32 shared base of H buffers
    const u32 Hbase = (u32)__cvta_generic_to_shared(smem);

    // per-mm offsets (m = (mm+wid)&3 stagger)
    int aofs[4], hoff[4], roff[4];
    {
        const int lrow_loc = ((l >> 3) & 1) * 8 + (l & 7);
        const int khalf = l >> 4;
        #pragma unroll
        for (int mm = 0; mm < 4; mm++) {
            int m = (mm + wid) & 3;
            aofs[mm] = (16 * m + lrow_loc) * (HROW * 4) + khalf * 16;
            hoff[mm] = (16 * m + q) * HROW + wp;
            roff[mm] = 16 * m + q;
        }
    }

    // ---- init H buffer 0 (plain fp16x2 word layout) ----
    {
        u32* H0 = (u32*)(smem + SM_H);
        for (int idx = tid; idx < TB * 32; idx += NTHR) {
            int row = idx >> 5, w = idx & 31;
            float2 hv = *(const float2*)(h0g + (size_t)(b0 + row) * 64 + 2 * w);
            H0[row * HROW + w] = f16pack(hv.x, hv.y);
        }
        for (int idx = tid; idx < TB * 8; idx += NTHR) {
            int row = idx >> 3, p = idx & 7;
            float2 tr = *(const float2*)(traj_rel + (size_t)(b0 + row) * 2);
            float4 w4 = *(const float4*)(sF + FI_WSE4 + 4 * p);
            float xa = w4.x * tr.x + w4.y * tr.y + sF[FI_BSE2 + 2 * p];
            float xb = w4.z * tr.x + w4.w * tr.y + sF[FI_BSE2 + 2 * p + 1];
            xa = (xa > 0.f) ? xa : 0.01f * xa;
            xb = (xb > 0.f) ? xb : 0.01f * xb;
            H0[row * HROW + 32 + p] = f16pack(xa, xb);
        }
    }

    // ---- c-state: creg[mm][rh][jj] ----
    float creg[4][2][2];
    #pragma unroll
    for (int mm = 0; mm < 4; mm++)
        #pragma unroll
        for (int rh = 0; rh < 2; rh++) {
            int row = roff[mm] + 8 * rh;
            float2 cv2 = *(const float2*)(c0g + (size_t)(b0 + row) * 64 + j0);
            creg[mm][rh][0] = cv2.x; creg[mm][rh][1] = cv2.y;
        }

    // ---- row-owner derived state (goal fold) -> SMEM (tid < 64, row = tid) ----
    if (tid < TB) {
        const int row = tid;
        float s0 = sF[FI_CG], s1 = sF[FI_CG + 1];
        const float* gp = goals + (size_t)(b0 + row) * 64;
        #pragma unroll 8
        for (int k = 0; k < 64; k++) {
            float gv = gp[k];
            s0 += sF[FI_MG + k] * gv;
            s1 += sF[FI_MG + 64 + k] * gv;
        }
        sF[FI_GOC + 2 * row] = s0; sF[FI_GOC + 2 * row + 1] = s1;
    }
    __syncthreads();

    // ---- tail state in registers ----
    const int trow = tid >> 2;           // tail: row owned by this thread
    const int tpart = tid & 3;           // tail: which partial pair
    const float cv0 = sF[FI_CV], cv1 = sF[FI_CV + 1];
    const float m200 = sF[FI_M2], m201 = sF[FI_M2 + 1];
    const float m210 = sF[FI_M2 + 2], m211 = sF[FI_M2 + 3];
    const float goc0 = sF[FI_GOC + 2 * trow], goc1 = sF[FI_GOC + 2 * trow + 1];
    const float4 wse_a = *(const float4*)(sF + FI_WSE4 + 4 * (2 * tpart));
    const float4 wse_b = *(const float4*)(sF + FI_WSE4 + 4 * (2 * tpart + 1));
    const float2 bse_a = *(const float2*)(sF + FI_BSE2 + 2 * (2 * tpart));
    const float2 bse_b = *(const float2*)(sF + FI_BSE2 + 2 * (2 * tpart + 1));
    // abs-position: private per tail thread (all 4 parts update identically)
    float ab0 = traj_abs[(size_t)(b0 + trow) * 2];
    float ab1 = traj_abs[(size_t)(b0 + trow) * 2 + 1];

    const u32 H05 = 0x38003800u;    // (0.5, 0.5) f16x2

    #pragma unroll 1
    for (int s = 0; s < SEQ; s++) {
        const u32 Hu = Hbase + (s & 1) * HBUF_BYTES;
        u32* N = (u32*)(smem + SM_H) + ((s + 1) & 1) * (HBUF_BYTES / 4);

        #pragma unroll
        for (int mm = 0; mm < 4; mm++) {
            // ---- A fragments via ldmatrix.x4 (5 per m-tile) ----
            u32 A[5][4];
            {
                const u32 ab = Hu + aofs[mm];
                #pragma unroll
                for (int kc = 0; kc < 5; kc++)
                    ldsm_x4(A[kc], ab + kc * 32);
            }
            // ---- MMA: bias-initialized accumulators ----
            float acc[4][4] = {
                { bI.x, bI.y, bI.x, bI.y },
                { bF.x, bF.y, bF.x, bF.y },
                { bG.x, bG.y, bG.x, bG.y },
                { bO.x, bO.y, bO.x, bO.y },
            };
            #pragma unroll
            for (int kc = 0; kc < 5; kc++)
                #pragma unroll
                for (int t = 0; t < 4; t++)
                    mma16816(acc[t], A[kc], (u32)Breg[kc][t], (u32)(Breg[kc][t] >> 32));

            // ---- f16x2 activation epilogue (c-recurrence in fp32) ----
            float rpm[2][2];
            #pragma unroll
            for (int rh = 0; rh < 2; rh++) {
                u32 I2 = f16pack(acc[0][2 * rh], acc[0][2 * rh + 1]);
                u32 F2 = f16pack(acc[1][2 * rh], acc[1][2 * rh + 1]);
                u32 G2 = f16pack(acc[2][2 * rh], acc[2][2 * rh + 1]);
                u32 O2 = f16pack(acc[3][2 * rh], acc[3][2 * rh + 1]);
                u32 si = hfma2(tanh_h2(hmul2(I2, H05)), H05, H05);
                u32 sf = hfma2(tanh_h2(hmul2(F2, H05)), H05, H05);
                u32 so = hfma2(tanh_h2(hmul2(O2, H05)), H05, H05);
                u32 tg = tanh_h2(G2);
                float2 pr = h2unpack(hmul2(si, tg));
                float2 sff = h2unpack(sf);
                float cn0 = fmaf(sff.x, creg[mm][rh][0], pr.x);
                float cn1 = fmaf(sff.y, creg[mm][rh][1], pr.y);
                creg[mm][rh][0] = cn0; creg[mm][rh][1] = cn1;
                u32 h2v = hmul2(so, tanh_h2(f16pack(cn0, cn1)));
                N[hoff[mm] + 8 * HROW * rh] = h2v;     // already packed
                float2 hf = h2unpack(h2v);
                rpm[rh][0] = w2q.x * hf.x + w2q.z * hf.y;
                rpm[rh][1] = w2q.y * hf.x + w2q.w * hf.y;
            }
            // quad butterfly -> warp partial for this warp's 8 j's
            #pragma unroll
            for (int rh = 0; rh < 2; rh++) {
                #pragma unroll
                for (int ax = 0; ax < 2; ax++) {
                    float v = rpm[rh][ax];
                    v += __shfl_xor_sync(0xFFFFFFFFu, v, 1);
                    v += __shfl_xor_sync(0xFFFFFFFFu, v, 2);
                    rpm[rh][ax] = v;
                }
            }
            if (c4 == 0) {
                #pragma unroll
                for (int rh = 0; rh < 2; rh++) {
                    int row = roff[mm] + 8 * rh;
                    *(float2*)(sF + FI_RELP + wid * RELPW + 2 * row) =
                        make_float2(rpm[rh][0], rpm[rh][1]);
                }
            }
        }
        __syncthreads();   // barrier A: h' + RELP visible

        // ---- rel finalization: 4 threads per row (row=tid>>2, part=tid&3) ----
        {
            float2 pa = *(const float2*)(sF + FI_RELP + (2 * tpart) * RELPW + 2 * trow);
            float2 pb = *(const float2*)(sF + FI_RELP + (2 * tpart + 1) * RELPW + 2 * trow);
            float r0 = pa.x + pb.x, r1 = pa.y + pb.y;
            r0 += __shfl_xor_sync(0xFFFFFFFFu, r0, 1);
            r0 += __shfl_xor_sync(0xFFFFFFFFu, r0, 2);
            r1 += __shfl_xor_sync(0xFFFFFFFFu, r1, 1);
            r1 += __shfl_xor_sync(0xFFFFFFFFu, r1, 2);
            r0 += cv0 + goc0 + m200 * ab0 + m201 * ab1;
            r1 += cv1 + goc1 + m210 * ab0 + m211 * ab1;
            if (tpart == 0)
                *(float2*)(out + ((size_t)s * Btot + b0 + trow) * 2) = make_float2(r0, r1);
            ab0 += r0; ab1 += r1;
            if (s < SEQ - 1) {
                float xa = wse_a.x * r0 + wse_a.y * r1 + bse_a.x;
                float xb = wse_a.z * r0 + wse_a.w * r1 + bse_a.y;
                xa = (xa > 0.f) ? xa : 0.01f * xa;
                xb = (xb > 0.f) ? xb : 0.01f * xb;
                N[trow * HROW + 32 + 2 * tpart] = f16pack(xa, xb);
                float xc = wse_b.x * r0 + wse_b.y * r1 + bse_b.x;
                float xd = wse_b.z * r0 + wse_b.w * r1 + bse_b.y;
                xc = (xc > 0.f) ? xc : 0.01f * xc;
                xd = (xd > 0.f) ? xd : 0.01f * xd;
                N[trow * HROW + 32 + 2 * tpart + 1] = f16pack(xc, xd);
            }
        }
        __syncthreads();   // barrier B: x' visible before next step's A loads
    }
}

// ============================================================================
extern "C" void kernel_launch(void* const* d_in, const int* in_sizes, int n_in,
                              void* d_out, int out_size)
{
    const float* traj_abs = (const float*)d_in[0];
    const float* traj_rel = (const float*)d_in[1];
    const float* h0       = (const float*)d_in[2];
    const float* c0       = (const float*)d_in[3];
    const float* goals    = (const float*)d_in[4];
    const float* W_ih     = (const float*)d_in[5];
    const float* W_hh     = (const float*)d_in[6];
    const float* b_ih     = (const float*)d_in[7];
    const float* b_hh     = (const float*)d_in[8];
    const float* W_se     = (const float*)d_in[9];
    const float* b_se     = (const float*)d_in[10];
    const float* W_h2p    = (const float*)d_in[11];
    const float* b_h2p    = (const float*)d_in[12];
    const float* W_goal   = (const float*)d_in[13];
    const float* b_goal   = (const float*)d_in[14];
    const float* W_abs    = (const float*)d_in[15];
    const float* b_abs    = (const float*)d_in[16];

    int B = in_sizes[2] / 64;

    cudaFuncSetAttribute(lstm_main, cudaFuncAttributeMaxDynamicSharedMemorySize, SMEM_BYTES);

    prep_kernel<<<1, NTHR>>>(W_ih, W_hh, b_ih, b_hh, W_h2p, b_h2p,
                             W_goal, b_goal, W_abs, b_abs, W_se, b_se);
    lstm_main<<<B / TB, NTHR, SMEM_BYTES>>>(traj_abs, traj_rel, h0, c0, goals,
                                            (float*)d_out, B);
}

// round 16
// speedup vs baseline: 1.1312x; 1.0759x over previous
#include <cuda_runtime.h>
#include <cuda_fp16.h>
#include <cstdint>

// GoalDecoderLSTM, B=131072, H=64, E=16, SEQ=30 — fp16 HMMA.
// R16 = R13 (B in registers, ldmatrix A, fp32 tanh.approx epilogue, parallel
// lean tail, m-stagger, occ 2, HROW=44 plain layout) + instruction diet:
//   * sigmoid 1/2-scale folded into i/f/o weight rows + biases in prep
//     (exact exponent shift -> bitwise-identical results, -3 FMUL/unit)
//   * tail x' pair stored as one STS.64
// CTA = 64 elems, 8 warps, occ 2. Warp w owns j in [8w,8w+8) (all 4 gates).

#define TB    64
#define SEQ   30
#define NTHR  256
#define HROW  44

// SMEM layout
#define SM_H       0                        // 2 bufs * 64*44*4 = 2*11264
#define HBUF_BYTES (TB * HROW * 4)
#define SM_F       (2*HBUF_BYTES)           // 22528
// float indices within sF
#define FI_BC    0      // 256
#define FI_W2P   256    // 128
#define FI_MG    384    // 128
#define FI_M2    512    // 4
#define FI_CV    516    // 2
#define FI_CG    518    // 2
#define FI_WSE4  520    // 32
#define FI_BSE2  552    // 16
#define FI_RELP  568    // 8 warps * 65 float2 = 1040 floats
#define RELPW    130    // floats per warp slot (padded: breaks 128-word alias)
#define FI_GOC   (FI_RELP + 8*RELPW)   // 128 floats
#define SF_FLOATS (FI_GOC + 128)
#define SMEM_BYTES (SM_F + SF_FLOATS*4)

typedef uint32_t u32;
typedef unsigned long long u64;

// ---- device staging (prep -> main) ----
__device__ __align__(16) u64 g_Bfrag[160 * 32];   // frag f = wid*20 + kc*4 + t
__device__ float g_bc[256];
__device__ float g_w2p[128];
__device__ float g_Mg[128];
__device__ float g_M2[4];
__device__ float g_cv[2];
__device__ float g_cg[2];
__device__ float g_wse4[32];
__device__ float g_bse2[16];

// ---- helpers ----
__device__ __forceinline__ u32 f16pack(float a, float b) {
    __half2 h = __floats2half2_rn(a, b);    // a -> low, b -> high
    return *(u32*)&h;
}
__device__ __forceinline__ void mma16816(float* d, const u32* a, u32 b0, u32 b1) {
    asm volatile("mma.sync.aligned.m16n8k16.row.col.f32.f16.f16.f32 "
        "{%0,%1,%2,%3}, {%4,%5,%6,%7}, {%8,%9}, {%0,%1,%2,%3};"
        : "+f"(d[0]), "+f"(d[1]), "+f"(d[2]), "+f"(d[3])
        : "r"(a[0]), "r"(a[1]), "r"(a[2]), "r"(a[3]), "r"(b0), "r"(b1));
}
__device__ __forceinline__ void ldsm_x4(u32* a, u32 addr) {
    asm volatile("ldmatrix.sync.aligned.m8n8.x4.shared.b16 {%0,%1,%2,%3}, [%4];"
        : "=r"(a[0]), "=r"(a[1]), "=r"(a[2]), "=r"(a[3]) : "r"(addr));
}
__device__ __forceinline__ float tanh_hw(float x) {
    float r; asm("tanh.approx.f32 %0, %1;" : "=f"(r) : "f"(x)); return r;
}
// i/f/o gate pre-activations arrive PRE-HALVED (0.5 folded into W,b):
// sig(x) = 0.5*tanh(0.5x)+0.5, and iv==0.5x already.
__device__ __forceinline__ float lstm_unit(float iv, float fv, float gv, float ov, float& cst) {
    float si = fmaf(0.5f, tanh_hw(iv), 0.5f);
    float sf = fmaf(0.5f, tanh_hw(fv), 0.5f);
    float tg = tanh_hw(gv);
    float so = fmaf(0.5f, tanh_hw(ov), 0.5f);
    float cn = fmaf(sf, cst, si * tg);
    cst = cn;
    return so * tanh_hw(cn);
}

// ============================================================================
// Prep: fold small matrices; build B fragments (fp16, per-warp-slice order).
// i/f/o weight rows (t != 2) and biases are pre-scaled by 0.5 (exact).
// ============================================================================
__global__ void prep_kernel(const float* __restrict__ W_ih, const float* __restrict__ W_hh,
                            const float* __restrict__ b_ih, const float* __restrict__ b_hh,
                            const float* __restrict__ W_h2p, const float* __restrict__ b_h2p,
                            const float* __restrict__ W_goal, const float* __restrict__ b_goal,
                            const float* __restrict__ W_abs, const float* __restrict__ b_abs,
                            const float* __restrict__ W_se, const float* __restrict__ b_se)
{
    int tid = threadIdx.x;
    // frag f = w*20 + kc*4 + t  (w = warp slice 0..7, j in [8w, 8w+8))
    for (int idx = tid; idx < 160 * 32; idx += NTHR) {
        int f = idx >> 5, l = idx & 31;
        int w = f / 20, r = f % 20, kc = r >> 2, t = r & 3;
        int jj = l >> 2, c4 = l & 3;
        int j = 8 * w + jj;
        int row = t * 64 + j;
        int k0 = 16 * kc + 2 * c4;
        const float sc = (t == 2) ? 1.0f : 0.5f;   // fold sigmoid half-scale
        float v[4];
        #pragma unroll
        for (int i = 0; i < 4; i++) {
            int k = k0 + (i & 1) + (i >> 1) * 8;
            v[i] = sc * ((k < 64) ? W_hh[row * 64 + k] : W_ih[row * 16 + (k - 64)]);
        }
        __half2 p0 = __floats2half2_rn(v[0], v[1]);
        __half2 p1 = __floats2half2_rn(v[2], v[3]);
        g_Bfrag[idx] = (u64)*(u32*)&p0 | ((u64)*(u32*)&p1 << 32);
    }
    {
        int j = tid & 63, t = tid >> 6, row = t * 64 + j;
        float sc = (t == 2) ? 1.0f : 0.5f;
        g_bc[tid] = sc * (b_ih[row] + b_hh[row]);
    }
    if (tid < 64) {
        g_w2p[2 * tid]     = W_h2p[tid];
        g_w2p[2 * tid + 1] = W_h2p[192 + tid];
    }
    if (tid < 128) {
        int r = tid >> 6, j = tid & 63;
        float s = 0.f;
        for (int m = 0; m < 64; m++) s += W_h2p[r * 192 + 128 + m] * W_goal[m * 64 + j];
        g_Mg[tid] = s;
    }
    if (tid < 4) {
        int r = tid >> 1, c = tid & 1;
        float s = 0.f;
        for (int m = 0; m < 64; m++) s += W_h2p[r * 192 + 64 + m] * W_abs[m * 2 + c];
        g_M2[tid] = s;
    }
    if (tid < 2) {
        float s = b_h2p[tid];
        for (int m = 0; m < 64; m++) s += W_h2p[tid * 192 + 64 + m] * b_abs[m];
        g_cv[tid] = s;
        float s2 = 0.f;
        for (int m = 0; m < 64; m++) s2 += W_h2p[tid * 192 + 128 + m] * b_goal[m];
        g_cg[tid] = s2;
    }
    if (tid < 8) {
        g_wse4[tid * 4 + 0] = W_se[(2 * tid) * 2 + 0];
        g_wse4[tid * 4 + 1] = W_se[(2 * tid) * 2 + 1];
        g_wse4[tid * 4 + 2] = W_se[(2 * tid + 1) * 2 + 0];
        g_wse4[tid * 4 + 3] = W_se[(2 * tid + 1) * 2 + 1];
        g_bse2[tid * 2 + 0] = b_se[2 * tid];
        g_bse2[tid * 2 + 1] = b_se[2 * tid + 1];
    }
}

// ============================================================================
// Main kernel: 64 elems/CTA, 8 warps, 2 CTAs/SM, B in registers
// ============================================================================
__global__ void __launch_bounds__(NTHR, 2)
lstm_main(const float* __restrict__ traj_abs, const float* __restrict__ traj_rel,
          const float* __restrict__ h0g, const float* __restrict__ c0g,
          const float* __restrict__ goals, float* __restrict__ out, int Btot)
{
    extern __shared__ __align__(16) char smem[];
    float* sF = (float*)(smem + SM_F);
    const int tid = threadIdx.x, l = tid & 31, wid = tid >> 5;
    const int c4 = l & 3, q = l >> 2;
    const int b0 = blockIdx.x * TB;

    // ---- fill sF from staging ----
    for (int i = tid; i < 256; i += NTHR) sF[FI_BC + i] = g_bc[i];
    if (tid < 128) { sF[FI_W2P + tid] = g_w2p[tid]; sF[FI_MG + tid] = g_Mg[tid]; }
    if (tid < 4)  sF[FI_M2 + tid] = g_M2[tid];
    if (tid < 2)  { sF[FI_CV + tid] = g_cv[tid]; sF[FI_CG + tid] = g_cg[tid]; }
    if (tid < 32) sF[FI_WSE4 + tid] = g_wse4[tid];
    if (tid < 16) sF[FI_BSE2 + tid] = g_bse2[tid];
    __syncthreads();

    // ---- B fragments into registers (persistent) ----
    u64 Breg[5][4];
    {
        const u64* gB = g_Bfrag + (size_t)wid * 20 * 32 + l;
        #pragma unroll
        for (int kc = 0; kc < 5; kc++)
            #pragma unroll
            for (int t = 0; t < 4; t++)
                Breg[kc][t] = gB[(kc * 4 + t) * 32];
    }
    // per-warp-lane constants: biases + w2 pairs for j0 = 8*wid + 2*c4
    const int j0 = 8 * wid + 2 * c4;
    const float2 bI = *(const float2*)(sF + FI_BC + j0);
    const float2 bF = *(const float2*)(sF + FI_BC + 64 + j0);
    const float2 bG = *(const float2*)(sF + FI_BC + 128 + j0);
    const float2 bO = *(const float2*)(sF + FI_BC + 192 + j0);
    const float4 w2q = *(const float4*)(sF + FI_W2P + 2 * j0);
    const int wp = 4 * wid + c4;            // h' store word position (plain)

    // u32 shared base of H buffers
    const u32 Hbase = (u32)__cvta_generic_to_shared(smem);

    // per-mm offsets (m = (mm+wid)&3 stagger)
    int aofs[4], hoff[4], roff[4];
    {
        const int lrow_loc = ((l >> 3) & 1) * 8 + (l & 7);
        const int khalf = l >> 4;
        #pragma unroll
        for (int mm = 0; mm < 4; mm++) {
            int m = (mm + wid) & 3;
            aofs[mm] = (16 * m + lrow_loc) * (HROW * 4) + khalf * 16;
            hoff[mm] = (16 * m + q) * HROW + wp;
            roff[mm] = 16 * m + q;
        }
    }

    // ---- init H buffer 0 (plain fp16x2 word layout) ----
    {
        u32* H0 = (u32*)(smem + SM_H);
        for (int idx = tid; idx < TB * 32; idx += NTHR) {
            int row = idx >> 5, w = idx & 31;
            float2 hv = *(const float2*)(h0g + (size_t)(b0 + row) * 64 + 2 * w);
            H0[row * HROW + w] = f16pack(hv.x, hv.y);
        }
        for (int idx = tid; idx < TB * 8; idx += NTHR) {
            int row = idx >> 3, p = idx & 7;
            float2 tr = *(const float2*)(traj_rel + (size_t)(b0 + row) * 2);
            float4 w4 = *(const float4*)(sF + FI_WSE4 + 4 * p);
            float xa = w4.x * tr.x + w4.y * tr.y + sF[FI_BSE2 + 2 * p];
            float xb = w4.z * tr.x + w4.w * tr.y + sF[FI_BSE2 + 2 * p + 1];
            xa = (xa > 0.f) ? xa : 0.01f * xa;
            xb = (xb > 0.f) ? xb : 0.01f * xb;
            H0[row * HROW + 32 + p] = f16pack(xa, xb);
        }
    }

    // ---- c-state: creg[mm][rh][jj] ----
    float creg[4][2][2];
    #pragma unroll
    for (int mm = 0; mm < 4; mm++)
        #pragma unroll
        for (int rh = 0; rh < 2; rh++) {
            int row = roff[mm] + 8 * rh;
            float2 cv2 = *(const float2*)(c0g + (size_t)(b0 + row) * 64 + j0);
            creg[mm][rh][0] = cv2.x; creg[mm][rh][1] = cv2.y;
        }

    // ---- row-owner derived state (goal fold) -> SMEM (tid < 64, row = tid) ----
    if (tid < TB) {
        const int row = tid;
        float s0 = sF[FI_CG], s1 = sF[FI_CG + 1];
        const float* gp = goals + (size_t)(b0 + row) * 64;
        #pragma unroll 8
        for (int k = 0; k < 64; k++) {
            float gv = gp[k];
            s0 += sF[FI_MG + k] * gv;
            s1 += sF[FI_MG + 64 + k] * gv;
        }
        sF[FI_GOC + 2 * row] = s0; sF[FI_GOC + 2 * row + 1] = s1;
    }
    __syncthreads();

    // ---- tail state in registers ----
    const int trow = tid >> 2;           // tail: row owned by this thread
    const int tpart = tid & 3;           // tail: which partial pair
    const float cv0 = sF[FI_CV], cv1 = sF[FI_CV + 1];
    const float m200 = sF[FI_M2], m201 = sF[FI_M2 + 1];
    const float m210 = sF[FI_M2 + 2], m211 = sF[FI_M2 + 3];
    const float goc0 = sF[FI_GOC + 2 * trow], goc1 = sF[FI_GOC + 2 * trow + 1];
    const float4 wse_a = *(const float4*)(sF + FI_WSE4 + 4 * (2 * tpart));
    const float4 wse_b = *(const float4*)(sF + FI_WSE4 + 4 * (2 * tpart + 1));
    const float2 bse_a = *(const float2*)(sF + FI_BSE2 + 2 * (2 * tpart));
    const float2 bse_b = *(const float2*)(sF + FI_BSE2 + 2 * (2 * tpart + 1));
    // abs-position: private per tail thread (all 4 parts update identically)
    float ab0 = traj_abs[(size_t)(b0 + trow) * 2];
    float ab1 = traj_abs[(size_t)(b0 + trow) * 2 + 1];

    #pragma unroll 1
    for (int s = 0; s < SEQ; s++) {
        const u32 Hu = Hbase + (s & 1) * HBUF_BYTES;
        u32* N = (u32*)(smem + SM_H) + ((s + 1) & 1) * (HBUF_BYTES / 4);

        #pragma unroll
        for (int mm = 0; mm < 4; mm++) {
            // ---- A fragments via ldmatrix.x4 (5 per m-tile) ----
            u32 A[5][4];
            {
                const u32 ab = Hu + aofs[mm];
                #pragma unroll
                for (int kc = 0; kc < 5; kc++)
                    ldsm_x4(A[kc], ab + kc * 32);
            }
            // ---- MMA: bias-initialized accumulators ----
            float acc[4][4] = {
                { bI.x, bI.y, bI.x, bI.y },
                { bF.x, bF.y, bF.x, bF.y },
                { bG.x, bG.y, bG.x, bG.y },
                { bO.x, bO.y, bO.x, bO.y },
            };
            #pragma unroll
            for (int kc = 0; kc < 5; kc++)
                #pragma unroll
                for (int t = 0; t < 4; t++)
                    mma16816(acc[t], A[kc], (u32)Breg[kc][t], (u32)(Breg[kc][t] >> 32));

            // ---- epilogue (i/f/o pre-halved by weight folding) ----
            float rpm[2][2];
            #pragma unroll
            for (int rh = 0; rh < 2; rh++) {
                float h0v = lstm_unit(acc[0][2 * rh], acc[1][2 * rh],
                                      acc[2][2 * rh], acc[3][2 * rh], creg[mm][rh][0]);
                float h1v = lstm_unit(acc[0][2 * rh + 1], acc[1][2 * rh + 1],
                                      acc[2][2 * rh + 1], acc[3][2 * rh + 1], creg[mm][rh][1]);
                rpm[rh][0] = w2q.x * h0v + w2q.z * h1v;
                rpm[rh][1] = w2q.y * h0v + w2q.w * h1v;
                N[hoff[mm] + 8 * HROW * rh] = f16pack(h0v, h1v);
            }
            // quad butterfly -> warp partial for this warp's 8 j's
            #pragma unroll
            for (int rh = 0; rh < 2; rh++) {
                #pragma unroll
                for (int ax = 0; ax < 2; ax++) {
                    float v = rpm[rh][ax];
                    v += __shfl_xor_sync(0xFFFFFFFFu, v, 1);
                    v += __shfl_xor_sync(0xFFFFFFFFu, v, 2);
                    rpm[rh][ax] = v;
                }
            }
            if (c4 == 0) {
                #pragma unroll
                for (int rh = 0; rh < 2; rh++) {
                    int row = roff[mm] + 8 * rh;
                    *(float2*)(sF + FI_RELP + wid * RELPW + 2 * row) =
                        make_float2(rpm[rh][0], rpm[rh][1]);
                }
            }
        }
        __syncthreads();   // barrier A: h' + RELP visible

        // ---- rel finalization: 4 threads per row (row=tid>>2, part=tid&3) ----
        {
            float2 pa = *(const float2*)(sF + FI_RELP + (2 * tpart) * RELPW + 2 * trow);
            float2 pb = *(const float2*)(sF + FI_RELP + (2 * tpart + 1) * RELPW + 2 * trow);
            float r0 = pa.x + pb.x, r1 = pa.y + pb.y;
            r0 += __shfl_xor_sync(0xFFFFFFFFu, r0, 1);
            r0 += __shfl_xor_sync(0xFFFFFFFFu, r0, 2);
            r1 += __shfl_xor_sync(0xFFFFFFFFu, r1, 1);
            r1 += __shfl_xor_sync(0xFFFFFFFFu, r1, 2);
            r0 += cv0 + goc0 + m200 * ab0 + m201 * ab1;
            r1 += cv1 + goc1 + m210 * ab0 + m211 * ab1;
            if (tpart == 0)
                *(float2*)(out + ((size_t)s * Btot + b0 + trow) * 2) = make_float2(r0, r1);
            ab0 += r0; ab1 += r1;
            if (s < SEQ - 1) {
                float xa = wse_a.x * r0 + wse_a.y * r1 + bse_a.x;
                float xb = wse_a.z * r0 + wse_a.w * r1 + bse_a.y;
                xa = (xa > 0.f) ? xa : 0.01f * xa;
                xb = (xb > 0.f) ? xb : 0.01f * xb;
                float xc = wse_b.x * r0 + wse_b.y * r1 + bse_b.x;
                float xd = wse_b.z * r0 + wse_b.w * r1 + bse_b.y;
                xc = (xc > 0.f) ? xc : 0.01f * xc;
                xd = (xd > 0.f) ? xd : 0.01f * xd;
                u64 xw = (u64)f16pack(xa, xb) | ((u64)f16pack(xc, xd) << 32);
                *(u64*)(N + trow * HROW + 32 + 2 * tpart) = xw;   // one STS.64
            }
        }
        __syncthreads();   // barrier B: x' visible before next step's A loads
    }
}

// ============================================================================
extern "C" void kernel_launch(void* const* d_in, const int* in_sizes, int n_in,
                              void* d_out, int out_size)
{
    const float* traj_abs = (const float*)d_in[0];
    const float* traj_rel = (const float*)d_in[1];
    const float* h0       = (const float*)d_in[2];
    const float* c0       = (const float*)d_in[3];
    const float* goals    = (const float*)d_in[4];
    const float* W_ih     = (const float*)d_in[5];
    const float* W_hh     = (const float*)d_in[6];
    const float* b_ih     = (const float*)d_in[7];
    const float* b_hh     = (const float*)d_in[8];
    const float* W_se     = (const float*)d_in[9];
    const float* b_se     = (const float*)d_in[10];
    const float* W_h2p    = (const float*)d_in[11];
    const float* b_h2p    = (const float*)d_in[12];
    const float* W_goal   = (const float*)d_in[13];
    const float* b_goal   = (const float*)d_in[14];
    const float* W_abs    = (const float*)d_in[15];
    const float* b_abs    = (const float*)d_in[16];

    int B = in_sizes[2] / 64;

    cudaFuncSetAttribute(lstm_main, cudaFuncAttributeMaxDynamicSharedMemorySize, SMEM_BYTES);

    prep_kernel<<<1, NTHR>>>(W_ih, W_hh, b_ih, b_hh, W_h2p, b_h2p,
                             W_goal, b_goal, W_abs, b_abs, W_se, b_se);
    lstm_main<<<B / TB, NTHR, SMEM_BYTES>>>(traj_abs, traj_rel, h0, c0, goals,
                                            (float*)d_out, B);
}

// round 17
// speedup vs baseline: 1.1744x; 1.0382x over previous
#include <cuda_runtime.h>
#include <cuda_fp16.h>
#include <cstdint>

// GoalDecoderLSTM, B=131072, H=64, E=16, SEQ=30 — fp16 HMMA.
// R17 = R16 (B in registers, ldmatrix A, folded-sigmoid fp32 tanh epilogue,
// m-stagger, occ 2) with the rel reduction replaced by a tiny MMA:
//   rel[64,2] = W2[2,64] @ h'[64,64]^T, W2 split hi/lo (exact).
//   Warps 0-3: 4 LDSM + 8 MMA on their 16-row block after barrier A;
//   c4==0 lanes finalize rel (+cv+goc+M2*ab), write out, post rel to SMEM.
//   All-thread x' tail (16 inst) after barrier B; barrier C guards reuse.
// Removes per-thread per-step: 32 FMA + 32 SHFL + RELP traffic.
// CTA = 64 elems, 8 warps, occ 2. Warp w owns j in [8w,8w+8) (all 4 gates).

#define TB    64
#define SEQ   30
#define NTHR  256
#define HROW  44

// SMEM layout
#define SM_H       0                        // 2 bufs * 64*44*4 = 2*11264
#define HBUF_BYTES (TB * HROW * 4)
#define SM_F       (2*HBUF_BYTES)           // 22528
// float indices within sF
#define FI_BC    0      // 256
#define FI_MG    256    // 128
#define FI_M2    384    // 4
#define FI_CV    388    // 2
#define FI_CG    390    // 2
#define FI_WSE4  392    // 32
#define FI_BSE2  424    // 16
#define FI_REL   440    // 128 (64 rows x float2)
#define FI_W2F   568    // 512 floats = 256 u64 (img,kc,lane), 8B aligned
#define SF_FLOATS (FI_W2F + 512)
#define SMEM_BYTES (SM_F + SF_FLOATS*4)

typedef uint32_t u32;
typedef unsigned long long u64;

// ---- device staging (prep -> main) ----
__device__ __align__(16) u64 g_Bfrag[160 * 32];   // frag f = wid*20 + kc*4 + t
__device__ __align__(16) u64 g_W2f[2 * 4 * 32];   // img(hi/lo), kc, lane
__device__ float g_bc[256];
__device__ float g_Mg[128];
__device__ float g_M2[4];
__device__ float g_cv[2];
__device__ float g_cg[2];
__device__ float g_wse4[32];
__device__ float g_bse2[16];

// ---- helpers ----
__device__ __forceinline__ u32 f16pack(float a, float b) {
    __half2 h = __floats2half2_rn(a, b);    // a -> low, b -> high
    return *(u32*)&h;
}
__device__ __forceinline__ void mma16816(float* d, const u32* a, u32 b0, u32 b1) {
    asm volatile("mma.sync.aligned.m16n8k16.row.col.f32.f16.f16.f32 "
        "{%0,%1,%2,%3}, {%4,%5,%6,%7}, {%8,%9}, {%0,%1,%2,%3};"
        : "+f"(d[0]), "+f"(d[1]), "+f"(d[2]), "+f"(d[3])
        : "r"(a[0]), "r"(a[1]), "r"(a[2]), "r"(a[3]), "r"(b0), "r"(b1));
}
__device__ __forceinline__ void ldsm_x4(u32* a, u32 addr) {
    asm volatile("ldmatrix.sync.aligned.m8n8.x4.shared.b16 {%0,%1,%2,%3}, [%4];"
        : "=r"(a[0]), "=r"(a[1]), "=r"(a[2]), "=r"(a[3]) : "r"(addr));
}
__device__ __forceinline__ float tanh_hw(float x) {
    float r; asm("tanh.approx.f32 %0, %1;" : "=f"(r) : "f"(x)); return r;
}
// i/f/o gate pre-activations arrive PRE-HALVED (0.5 folded into W,b).
__device__ __forceinline__ float lstm_unit(float iv, float fv, float gv, float ov, float& cst) {
    float si = fmaf(0.5f, tanh_hw(iv), 0.5f);
    float sf = fmaf(0.5f, tanh_hw(fv), 0.5f);
    float tg = tanh_hw(gv);
    float so = fmaf(0.5f, tanh_hw(ov), 0.5f);
    float cn = fmaf(sf, cst, si * tg);
    cst = cn;
    return so * tanh_hw(cn);
}

// ============================================================================
// Prep: fold small matrices; build B fragments + W2 hi/lo fragments
// ============================================================================
__global__ void prep_kernel(const float* __restrict__ W_ih, const float* __restrict__ W_hh,
                            const float* __restrict__ b_ih, const float* __restrict__ b_hh,
                            const float* __restrict__ W_h2p, const float* __restrict__ b_h2p,
                            const float* __restrict__ W_goal, const float* __restrict__ b_goal,
                            const float* __restrict__ W_abs, const float* __restrict__ b_abs,
                            const float* __restrict__ W_se, const float* __restrict__ b_se)
{
    int tid = threadIdx.x;
    // gate B frags: f = w*20 + kc*4 + t  (w = warp slice 0..7, j in [8w, 8w+8))
    for (int idx = tid; idx < 160 * 32; idx += NTHR) {
        int f = idx >> 5, l = idx & 31;
        int w = f / 20, r = f % 20, kc = r >> 2, t = r & 3;
        int jj = l >> 2, c4 = l & 3;
        int j = 8 * w + jj;
        int row = t * 64 + j;
        int k0 = 16 * kc + 2 * c4;
        const float sc = (t == 2) ? 1.0f : 0.5f;   // fold sigmoid half-scale
        float v[4];
        #pragma unroll
        for (int i = 0; i < 4; i++) {
            int k = k0 + (i & 1) + (i >> 1) * 8;
            v[i] = sc * ((k < 64) ? W_hh[row * 64 + k] : W_ih[row * 16 + (k - 64)]);
        }
        __half2 p0 = __floats2half2_rn(v[0], v[1]);
        __half2 p1 = __floats2half2_rn(v[2], v[3]);
        g_Bfrag[idx] = (u64)*(u32*)&p0 | ((u64)*(u32*)&p1 << 32);
    }
    // W2 fragments (hi/lo): B-operand of rel-MMA; n=jj (rows of W2, <2 real)
    for (int idx = tid; idx < 256; idx += NTHR) {
        int l = idx & 31, kc = (idx >> 5) & 3, img = idx >> 7;
        int jj = l >> 2, c4 = l & 3;
        float v[4];
        #pragma unroll
        for (int i = 0; i < 4; i++) {
            int j = 16 * kc + 2 * c4 + (i & 1) + (i >> 1) * 8;
            float w = (jj < 2) ? W_h2p[jj * 192 + j] : 0.f;
            __half hh = __float2half_rn(w);
            v[i] = (img == 0) ? __half2float(hh) : (w - __half2float(hh));
        }
        __half2 p0 = __floats2half2_rn(v[0], v[1]);
        __half2 p1 = __floats2half2_rn(v[2], v[3]);
        g_W2f[idx] = (u64)*(u32*)&p0 | ((u64)*(u32*)&p1 << 32);
    }
    {
        int j = tid & 63, t = tid >> 6, row = t * 64 + j;
        float sc = (t == 2) ? 1.0f : 0.5f;
        g_bc[tid] = sc * (b_ih[row] + b_hh[row]);
    }
    if (tid < 128) {
        int r = tid >> 6, j = tid & 63;
        float s = 0.f;
        for (int m = 0; m < 64; m++) s += W_h2p[r * 192 + 128 + m] * W_goal[m * 64 + j];
        g_Mg[tid] = s;
    }
    if (tid < 4) {
        int r = tid >> 1, c = tid & 1;
        float s = 0.f;
        for (int m = 0; m < 64; m++) s += W_h2p[r * 192 + 64 + m] * W_abs[m * 2 + c];
        g_M2[tid] = s;
    }
    if (tid < 2) {
        float s = b_h2p[tid];
        for (int m = 0; m < 64; m++) s += W_h2p[tid * 192 + 64 + m] * b_abs[m];
        g_cv[tid] = s;
        float s2 = 0.f;
        for (int m = 0; m < 64; m++) s2 += W_h2p[tid * 192 + 128 + m] * b_goal[m];
        g_cg[tid] = s2;
    }
    if (tid < 8) {
        g_wse4[tid * 4 + 0] = W_se[(2 * tid) * 2 + 0];
        g_wse4[tid * 4 + 1] = W_se[(2 * tid) * 2 + 1];
        g_wse4[tid * 4 + 2] = W_se[(2 * tid + 1) * 2 + 0];
        g_wse4[tid * 4 + 3] = W_se[(2 * tid + 1) * 2 + 1];
        g_bse2[tid * 2 + 0] = b_se[2 * tid];
        g_bse2[tid * 2 + 1] = b_se[2 * tid + 1];
    }
}

// ============================================================================
// Main kernel: 64 elems/CTA, 8 warps, 2 CTAs/SM, B in registers
// ============================================================================
__global__ void __launch_bounds__(NTHR, 2)
lstm_main(const float* __restrict__ traj_abs, const float* __restrict__ traj_rel,
          const float* __restrict__ h0g, const float* __restrict__ c0g,
          const float* __restrict__ goals, float* __restrict__ out, int Btot)
{
    extern __shared__ __align__(16) char smem[];
    float* sF = (float*)(smem + SM_F);
    const int tid = threadIdx.x, l = tid & 31, wid = tid >> 5;
    const int c4 = l & 3, q = l >> 2;
    const int b0 = blockIdx.x * TB;

    // ---- fill sF from staging ----
    for (int i = tid; i < 256; i += NTHR) sF[FI_BC + i] = g_bc[i];
    {
        const u64* src = g_W2f;
        u64* dst = (u64*)(sF + FI_W2F);
        for (int i = tid; i < 256; i += NTHR) dst[i] = src[i];
    }
    if (tid < 128) sF[FI_MG + tid] = g_Mg[tid];
    if (tid < 4)  sF[FI_M2 + tid] = g_M2[tid];
    if (tid < 2)  { sF[FI_CV + tid] = g_cv[tid]; sF[FI_CG + tid] = g_cg[tid]; }
    if (tid < 32) sF[FI_WSE4 + tid] = g_wse4[tid];
    if (tid < 16) sF[FI_BSE2 + tid] = g_bse2[tid];
    __syncthreads();

    // ---- B fragments into registers (persistent) ----
    u64 Breg[5][4];
    {
        const u64* gB = g_Bfrag + (size_t)wid * 20 * 32 + l;
        #pragma unroll
        for (int kc = 0; kc < 5; kc++)
            #pragma unroll
            for (int t = 0; t < 4; t++)
                Breg[kc][t] = gB[(kc * 4 + t) * 32];
    }
    // per-warp-lane constants: biases for j0 = 8*wid + 2*c4
    const int j0 = 8 * wid + 2 * c4;
    const float2 bI = *(const float2*)(sF + FI_BC + j0);
    const float2 bF = *(const float2*)(sF + FI_BC + 64 + j0);
    const float2 bG = *(const float2*)(sF + FI_BC + 128 + j0);
    const float2 bO = *(const float2*)(sF + FI_BC + 192 + j0);
    const int wp = 4 * wid + c4;            // h' store word position (plain)

    const u32 Hbase = (u32)__cvta_generic_to_shared(smem);

    // per-mm offsets (m = (mm+wid)&3 stagger)
    int aofs[4], hoff[4], roff[4];
    int rofs;                               // rel-MMA ldsm offset (wid<4)
    {
        const int lrow_loc = ((l >> 3) & 1) * 8 + (l & 7);
        const int khalf = l >> 4;
        #pragma unroll
        for (int mm = 0; mm < 4; mm++) {
            int m = (mm + wid) & 3;
            aofs[mm] = (16 * m + lrow_loc) * (HROW * 4) + khalf * 16;
            hoff[mm] = (16 * m + q) * HROW + wp;
            roff[mm] = 16 * m + q;
        }
        rofs = (16 * (wid & 3) + lrow_loc) * (HROW * 4) + khalf * 16;
    }

    // ---- init H buffer 0 (plain fp16x2 word layout) ----
    {
        u32* H0 = (u32*)(smem + SM_H);
        for (int idx = tid; idx < TB * 32; idx += NTHR) {
            int row = idx >> 5, w = idx & 31;
            float2 hv = *(const float2*)(h0g + (size_t)(b0 + row) * 64 + 2 * w);
            H0[row * HROW + w] = f16pack(hv.x, hv.y);
        }
        for (int idx = tid; idx < TB * 8; idx += NTHR) {
            int row = idx >> 3, p = idx & 7;
            float2 tr = *(const float2*)(traj_rel + (size_t)(b0 + row) * 2);
            float4 w4 = *(const float4*)(sF + FI_WSE4 + 4 * p);
            float xa = w4.x * tr.x + w4.y * tr.y + sF[FI_BSE2 + 2 * p];
            float xb = w4.z * tr.x + w4.w * tr.y + sF[FI_BSE2 + 2 * p + 1];
            xa = (xa > 0.f) ? xa : 0.01f * xa;
            xb = (xb > 0.f) ? xb : 0.01f * xb;
            H0[row * HROW + 32 + p] = f16pack(xa, xb);
        }
    }

    // ---- c-state: creg[mm][rh][jj] ----
    float creg[4][2][2];
    #pragma unroll
    for (int mm = 0; mm < 4; mm++)
        #pragma unroll
        for (int rh = 0; rh < 2; rh++) {
            int row = roff[mm] + 8 * rh;
            float2 cv2 = *(const float2*)(c0g + (size_t)(b0 + row) * 64 + j0);
            creg[mm][rh][0] = cv2.x; creg[mm][rh][1] = cv2.y;
        }

    // ---- rel-lane state: rows 16*wid + q (+8). Valid for wid<4, c4==0. ----
    const float cv0 = sF[FI_CV], cv1 = sF[FI_CV + 1];
    const float m200 = sF[FI_M2], m201 = sF[FI_M2 + 1];
    const float m210 = sF[FI_M2 + 2], m211 = sF[FI_M2 + 3];
    float ab[2][2], goc[2][2];
    if (wid < 4 && c4 == 0) {
        #pragma unroll
        for (int rr = 0; rr < 2; rr++) {
            int row = 16 * wid + q + 8 * rr;
            ab[rr][0] = traj_abs[(size_t)(b0 + row) * 2];
            ab[rr][1] = traj_abs[(size_t)(b0 + row) * 2 + 1];
            float s0 = sF[FI_CG], s1 = sF[FI_CG + 1];
            const float* gp = goals + (size_t)(b0 + row) * 64;
            #pragma unroll 8
            for (int k = 0; k < 64; k++) {
                float gv = gp[k];
                s0 += sF[FI_MG + k] * gv;
                s1 += sF[FI_MG + 64 + k] * gv;
            }
            goc[rr][0] = s0; goc[rr][1] = s1;
        }
    }

    // ---- x'-tail constants (all threads; trow = tid>>2, tpart = tid&3) ----
    const int trow = tid >> 2;
    const int tpart = tid & 3;
    const float4 wse_a = *(const float4*)(sF + FI_WSE4 + 4 * (2 * tpart));
    const float4 wse_b = *(const float4*)(sF + FI_WSE4 + 4 * (2 * tpart + 1));
    const float2 bse_a = *(const float2*)(sF + FI_BSE2 + 2 * (2 * tpart));
    const float2 bse_b = *(const float2*)(sF + FI_BSE2 + 2 * (2 * tpart + 1));
    __syncthreads();

    #pragma unroll 1
    for (int s = 0; s < SEQ; s++) {
        const u32 Hu = Hbase + (s & 1) * HBUF_BYTES;
        const u32 Nu = Hbase + ((s + 1) & 1) * HBUF_BYTES;
        u32* N = (u32*)(smem + SM_H) + ((s + 1) & 1) * (HBUF_BYTES / 4);

        #pragma unroll
        for (int mm = 0; mm < 4; mm++) {
            // ---- A fragments via ldmatrix.x4 (5 per m-tile) ----
            u32 A[5][4];
            {
                const u32 ab2 = Hu + aofs[mm];
                #pragma unroll
                for (int kc = 0; kc < 5; kc++)
                    ldsm_x4(A[kc], ab2 + kc * 32);
            }
            // ---- MMA: bias-initialized accumulators ----
            float acc[4][4] = {
                { bI.x, bI.y, bI.x, bI.y },
                { bF.x, bF.y, bF.x, bF.y },
                { bG.x, bG.y, bG.x, bG.y },
                { bO.x, bO.y, bO.x, bO.y },
            };
            #pragma unroll
            for (int kc = 0; kc < 5; kc++)
                #pragma unroll
                for (int t = 0; t < 4; t++)
                    mma16816(acc[t], A[kc], (u32)Breg[kc][t], (u32)(Breg[kc][t] >> 32));

            // ---- epilogue: just activations + h' store ----
            #pragma unroll
            for (int rh = 0; rh < 2; rh++) {
                float h0v = lstm_unit(acc[0][2 * rh], acc[1][2 * rh],
                                      acc[2][2 * rh], acc[3][2 * rh], creg[mm][rh][0]);
                float h1v = lstm_unit(acc[0][2 * rh + 1], acc[1][2 * rh + 1],
                                      acc[2][2 * rh + 1], acc[3][2 * rh + 1], creg[mm][rh][1]);
                N[hoff[mm] + 8 * HROW * rh] = f16pack(h0v, h1v);
            }
        }
        __syncthreads();   // barrier A: h' visible

        // ---- rel via MMA: warps 0-3, m-tile = wid ----
        if (wid < 4) {
            u32 Ar[4][4];
            const u32 ab2 = Nu + rofs;
            #pragma unroll
            for (int kc = 0; kc < 4; kc++)
                ldsm_x4(Ar[kc], ab2 + kc * 32);
            float acc[4] = { cv0, cv1, cv0, cv1 };
            const u64* w2f = (const u64*)(sF + FI_W2F);
            #pragma unroll
            for (int kc = 0; kc < 4; kc++) {
                u64 whi = w2f[kc * 32 + l];
                u64 wlo = w2f[128 + kc * 32 + l];
                mma16816(acc, Ar[kc], (u32)whi, (u32)(whi >> 32));
                mma16816(acc, Ar[kc], (u32)wlo, (u32)(wlo >> 32));
            }
            if (c4 == 0) {
                #pragma unroll
                for (int rr = 0; rr < 2; rr++) {
                    const int row = 16 * wid + q + 8 * rr;
                    float r0 = acc[2 * rr]     + goc[rr][0] + m200 * ab[rr][0] + m201 * ab[rr][1];
                    float r1 = acc[2 * rr + 1] + goc[rr][1] + m210 * ab[rr][0] + m211 * ab[rr][1];
                    *(float2*)(out + ((size_t)s * Btot + b0 + row) * 2) = make_float2(r0, r1);
                    ab[rr][0] += r0; ab[rr][1] += r1;
                    *(float2*)(sF + FI_REL + 2 * row) = make_float2(r0, r1);
                }
            }
        }
        __syncthreads();   // barrier B: rel visible

        // ---- x' tail: all threads, 4 per row ----
        if (s < SEQ - 1) {
            float2 rv = *(const float2*)(sF + FI_REL + 2 * trow);
            float xa = wse_a.x * rv.x + wse_a.y * rv.y + bse_a.x;
            float xb = wse_a.z * rv.x + wse_a.w * rv.y + bse_a.y;
            xa = (xa > 0.f) ? xa : 0.01f * xa;
            xb = (xb > 0.f) ? xb : 0.01f * xb;
            float xc = wse_b.x * rv.x + wse_b.y * rv.y + bse_b.x;
            float xd = wse_b.z * rv.x + wse_b.w * rv.y + bse_b.y;
            xc = (xc > 0.f) ? xc : 0.01f * xc;
            xd = (xd > 0.f) ? xd : 0.01f * xd;
            u64 xw = (u64)f16pack(xa, xb) | ((u64)f16pack(xc, xd) << 32);
            *(u64*)(N + trow * HROW + 32 + 2 * tpart) = xw;   // one STS.64
            __syncthreads();   // barrier C: x' visible before next step's reads
        }
    }
}

// ============================================================================
extern "C" void kernel_launch(void* const* d_in, const int* in_sizes, int n_in,
                              void* d_out, int out_size)
{
    const float* traj_abs = (const float*)d_in[0];
    const float* traj_rel = (const float*)d_in[1];
    const float* h0       = (const float*)d_in[2];
    const float* c0       = (const float*)d_in[3];
    const float* goals    = (const float*)d_in[4];
    const float* W_ih     = (const float*)d_in[5];
    const float* W_hh     = (const float*)d_in[6];
    const float* b_ih     = (const float*)d_in[7];
    const float* b_hh     = (const float*)d_in[8];
    const float* W_se     = (const float*)d_in[9];
    const float* b_se     = (const float*)d_in[10];
    const float* W_h2p    = (const float*)d_in[11];
    const float* b_h2p    = (const float*)d_in[12];
    const float* W_goal   = (const float*)d_in[13];
    const float* b_goal   = (const float*)d_in[14];
    const float* W_abs    = (const float*)d_in[15];
    const float* b_abs    = (const float*)d_in[16];

    int B = in_sizes[2] / 64;

    cudaFuncSetAttribute(lstm_main, cudaFuncAttributeMaxDynamicSharedMemorySize, SMEM_BYTES);

    prep_kernel<<<1, NTHR>>>(W_ih, W_hh, b_ih, b_hh, W_h2p, b_h2p,
                             W_goal, b_goal, W_abs, b_abs, W_se, b_se);
    lstm_main<<<B / TB, NTHR, SMEM_BYTES>>>(traj_abs, traj_rel, h0, c0, goals,
                                            (float*)d_out, B);
}